// round 11
// baseline (speedup 1.0000x reference)
#include <cuda_runtime.h>
#include <math.h>

// ---------------- static device scratch (no allocations allowed) ----------------
#define B_ 8
__device__ float g_fusion[B_*48*256*256];   // curve outputs, un-normalized
__device__ float g_x1[B_*32*128*128];
__device__ float g_x2[B_*64*64*64];
__device__ float g_x3[B_*128*32*32];
__device__ float g_x4[B_*128*32*32];
__device__ float g_c5[B_*64*32*32];
__device__ float g_x5[B_*64*64*64];
__device__ float g_c6[B_*32*64*64];
__device__ float g_x6[B_*32*128*128];
__device__ float g_c7[B_*32*128*128];
__device__ float g_u7[B_*32*256*256];
__device__ float g_bnsums[992];
__device__ float g_sc3[48], g_sh3[48];
__device__ float g_sc7[64], g_sh7[64];     // [bn32a | bn32b]
__device__ float g_sc6[128], g_sh6[128];   // [bn64a | bn64b]
__device__ float g_sc5[256], g_sh5[256];   // [bn128b | bn128a]
__device__ float g_wm[33];                 // channel-mean of w11, b11

// sums layout offsets (each region: [sum C][sumsq C])
#define OFF3    0    // 96
#define OFF32A  96   // 64
#define OFF64A  160  // 128
#define OFF128A 288  // 256
#define OFF128B 544  // 256
#define OFF64B  800  // 128
#define OFF32B  928  // 64

// ---------------- tiny kernels ----------------
__global__ void zero_stats_kernel(float* s) { s[threadIdx.x] = 0.f; }

__global__ void finalize_bn_kernel(const float* __restrict__ sums, int C, float invN,
                                   const float* __restrict__ gam, const float* __restrict__ bet,
                                   int gmod, float* __restrict__ sc, float* __restrict__ sh)
{
    int c = threadIdx.x;
    if (c >= C) return;
    float m = sums[c] * invN;
    float v = fmaxf(sums[C + c] * invN - m * m, 0.f);
    int gi = gmod ? (c % gmod) : c;
    float s = gam[gi] * rsqrtf(v + 1e-5f);
    sc[c] = s;
    sh[c] = bet[gi] - m * s;
}

__global__ void finalize_w11_kernel(const float* __restrict__ w11, const float* __restrict__ b11,
                                    float* __restrict__ wm)
{
    int t = threadIdx.x;
    if (t < 32)      wm[t]  = (w11[t] + w11[32 + t] + w11[64 + t]) * (1.f / 3.f);
    else if (t == 32) wm[32] = (b11[0] + b11[1] + b11[2]) * (1.f / 3.f);
}

// ---------------- curve kernel: 16 enhancement branches + BN3 stats ----------------
__global__ void curve_kernel(const float* __restrict__ x, const float* __restrict__ n16,
                             const float* __restrict__ sig, const float* __restrict__ bias,
                             float* __restrict__ fusion, float* __restrict__ sums)
{
    __shared__ float s_n[16], s_d[16];
    int tid = threadIdx.x;
    if (tid < 16) {
        float n = n16[tid];
        s_n[tid] = n;
        s_d[tid] = exp2f(n * log2f(sig[tid])) + bias[tid];
    }
    __syncthreads();

    int idx = blockIdx.x * 256 + tid;         // over B*3*256*256, one row per block
    int hw = idx & 65535;
    int bc = idx >> 16;
    int c = bc % 3, b = bc / 3;

    float xv = x[idx];
    float l = log2f(xv);
    float sm[16], sq[16];
#pragma unroll
    for (int k = 0; k < 16; k++) {
        float xn = exp2f(s_n[k] * l);
        float r = xn / (xn + s_d[k]);
        fusion[((b * 48 + k * 3 + c) << 16) + hw] = r;
        sm[k] = r; sq[k] = r * r;
    }
    // warp reduce each of 16 (sum,sq)
#pragma unroll
    for (int k = 0; k < 16; k++) {
        float s = sm[k], q = sq[k];
        for (int o = 16; o; o >>= 1) {
            s += __shfl_xor_sync(0xFFFFFFFFu, s, o);
            q += __shfl_xor_sync(0xFFFFFFFFu, q, o);
        }
        sm[k] = s; sq[k] = q;
    }
    __shared__ float red[16][2][8];
    int wp = tid >> 5, ln = tid & 31;
    if (ln == 0) {
#pragma unroll
        for (int k = 0; k < 16; k++) { red[k][0][wp] = sm[k]; red[k][1][wp] = sq[k]; }
    }
    __syncthreads();
    if (tid < 32) {
        int k = tid >> 1, which = tid & 1;
        float v = 0.f;
#pragma unroll
        for (int i = 0; i < 8; i++) v += red[k][which][i];
        atomicAdd(&sums[which * 48 + k * 3 + c], v);
    }
}

// ---------------- templated 3x3 conv (+affine-in, +bias, +prelu, +pool, +stats) ----------------
template<int CIN0, int CIN1, int COUT, int COG, int TW, int TH, bool PRELU, bool POOL, bool STATS>
__global__ void __launch_bounds__((TW / 2) * (TH / 2))
conv3x3_kernel(const float* __restrict__ in0, const float* __restrict__ in1,
               const float* __restrict__ sc, const float* __restrict__ sh,
               const float* __restrict__ Wt, const float* __restrict__ Bs,
               const float* __restrict__ pa_ptr,
               float* __restrict__ out, float* __restrict__ stats,
               int H, int Wd)
{
    constexpr int CIN = CIN0 + CIN1;
    constexpr int CH = 8;
    constexpr int NT = (TW / 2) * (TH / 2);
    constexpr int IW = TW + 3;     // padded row stride (odd) to cut bank conflicts
    constexpr int NW = NT / 32;

    __shared__ float s_in[CH][TH + 2][IW];
    __shared__ float s_w[CH * 9 * COG];
    __shared__ float red[2][COG][NW];

    int tid = threadIdx.x;
    constexpr int GPB = COUT / COG;
    int b = blockIdx.z / GPB, g = blockIdx.z % GPB;
    int tx = blockIdx.x * TW, ty = blockIdx.y * TH;
    float pa = PRELU ? pa_ptr[0] : 0.f;

    float acc[4 * COG];
#pragma unroll
    for (int i = 0; i < 4 * COG; i++) acc[i] = 0.f;

    int qx = (tid % (TW / 2)) * 2, qy = (tid / (TW / 2)) * 2;

    for (int c0 = 0; c0 < CIN; c0 += CH) {
        // cooperative input tile load (affine applied; OOB -> 0 = post-BN zero pad)
        constexpr int TOT = CH * (TH + 2) * (TW + 2);
        for (int i = tid; i < TOT; i += NT) {
            int ci = i / ((TH + 2) * (TW + 2));
            int r = i - ci * ((TH + 2) * (TW + 2));
            int ly = r / (TW + 2), lx = r - ly * (TW + 2);
            int gy = ty + ly - 1, gx = tx + lx - 1;
            int cg = c0 + ci;
            float v = 0.f;
            if (gy >= 0 && gy < H && gx >= 0 && gx < Wd) {
                float raw;
                if (CIN1 == 0 || cg < CIN0)
                    raw = in0[((b * CIN0 + cg) * H + gy) * Wd + gx];
                else
                    raw = in1[((b * CIN1 + (cg - CIN0)) * H + gy) * Wd + gx];
                v = fmaf(raw, sc[cg], sh[cg]);
            }
            s_in[ci][ly][lx] = v;
        }
        // weight chunk load: layout [ci][tap][co]
        for (int i = tid; i < CH * 9 * COG; i += NT) {
            int co = i % COG; int t2 = i / COG; int tap = t2 % 9; int ci = t2 / 9;
            s_w[i] = Wt[((g * COG + co) * CIN + c0 + ci) * 9 + tap];
        }
        __syncthreads();

        for (int ci = 0; ci < CH; ci++) {
            float iv[4][4];
#pragma unroll
            for (int a = 0; a < 4; a++)
#pragma unroll
                for (int bb = 0; bb < 4; bb++) iv[a][bb] = s_in[ci][qy + a][qx + bb];
#pragma unroll
            for (int dy = 0; dy < 3; dy++)
#pragma unroll
                for (int dx = 0; dx < 3; dx++) {
                    const float* wrow = &s_w[(ci * 9 + dy * 3 + dx) * COG];
#pragma unroll
                    for (int co = 0; co < COG; co++) {
                        float wv = wrow[co];  // broadcast LDS feeds 4 FFMAs
                        acc[co * 4 + 0] += wv * iv[dy][dx];
                        acc[co * 4 + 1] += wv * iv[dy][dx + 1];
                        acc[co * 4 + 2] += wv * iv[dy + 1][dx];
                        acc[co * 4 + 3] += wv * iv[dy + 1][dx + 1];
                    }
                }
        }
        __syncthreads();
    }

    // epilogue: bias, prelu, pool, store, BN-stat accumulate
    int wp = tid >> 5, ln = tid & 31;
    int HO = POOL ? H / 2 : H, WO = POOL ? Wd / 2 : Wd;
#pragma unroll
    for (int co = 0; co < COG; co++) {
        int gco = g * COG + co;
        float bsv = Bs[gco];
        float v0 = acc[co * 4 + 0] + bsv, v1 = acc[co * 4 + 1] + bsv;
        float v2 = acc[co * 4 + 2] + bsv, v3 = acc[co * 4 + 3] + bsv;
        if (PRELU) {
            v0 = v0 >= 0.f ? v0 : pa * v0; v1 = v1 >= 0.f ? v1 : pa * v1;
            v2 = v2 >= 0.f ? v2 : pa * v2; v3 = v3 >= 0.f ? v3 : pa * v3;
        }
        float ssum, ssq;
        if (POOL) {
            float m = fmaxf(fmaxf(v0, v1), fmaxf(v2, v3));
            int oy = (ty + qy) >> 1, ox = (tx + qx) >> 1;
            out[((b * COUT + gco) * HO + oy) * WO + ox] = m;
            ssum = m; ssq = m * m;
        } else {
            int oy = ty + qy, ox = tx + qx;
            float* op = &out[((b * COUT + gco) * HO + oy) * WO + ox];
            op[0] = v0; op[1] = v1; op[WO] = v2; op[WO + 1] = v3;
            ssum = v0 + v1 + v2 + v3;
            ssq = v0 * v0 + v1 * v1 + v2 * v2 + v3 * v3;
        }
        if (STATS) {
            for (int o = 16; o; o >>= 1) {
                ssum += __shfl_xor_sync(0xFFFFFFFFu, ssum, o);
                ssq  += __shfl_xor_sync(0xFFFFFFFFu, ssq, o);
            }
            if (ln == 0) { red[0][co][wp] = ssum; red[1][co][wp] = ssq; }
        }
    }
    if (STATS) {
        __syncthreads();
        if (tid < 2 * COG) {
            int which = tid / COG, co = tid % COG;
            float v = 0.f;
#pragma unroll
            for (int i = 0; i < NW; i++) v += red[which][co][i];
            atomicAdd(&stats[which * COUT + g * COG + co], v);
        }
    }
}

// ---------------- bilinear x2 upsample (align_corners), optional stats / sigmoid ----------------
template<bool STATS, bool SIG>
__global__ void upsample2_kernel(const float* __restrict__ in, float* __restrict__ out,
                                 float* __restrict__ stats, int C, int H, int Wd)
{
    int H2 = 2 * H, W2 = 2 * Wd;
    int c = blockIdx.y, b = blockIdx.z;
    int idx = blockIdx.x * blockDim.x + threadIdx.x;
    int oy = idx / W2, ox = idx % W2;

    float py = (float)(oy * (H - 1)) / (float)(2 * H - 1);
    int ly = (int)floorf(py); int hy = min(ly + 1, H - 1); float fy = py - (float)ly;
    float px = (float)(ox * (Wd - 1)) / (float)(2 * Wd - 1);
    int lx = (int)floorf(px); int hx = min(lx + 1, Wd - 1); float fx = px - (float)lx;

    const float* ip = in + ((size_t)(b * C + c) * H) * Wd;
    float a00 = ip[ly * Wd + lx], a01 = ip[ly * Wd + hx];
    float a10 = ip[hy * Wd + lx], a11 = ip[hy * Wd + hx];
    float r0 = a00 * (1.f - fy) + a10 * fy;     // rows first (matches reference order)
    float r1 = a01 * (1.f - fy) + a11 * fy;
    float v = r0 * (1.f - fx) + r1 * fx;
    if (SIG) v = 1.f / (1.f + expf(-v));
    out[((size_t)(b * C + c) * H2 + oy) * W2 + ox] = v;

    if (STATS) {
        float s = v, q = v * v;
        for (int o = 16; o; o >>= 1) {
            s += __shfl_xor_sync(0xFFFFFFFFu, s, o);
            q += __shfl_xor_sync(0xFFFFFFFFu, q, o);
        }
        __shared__ float red[2][8];
        int wp = threadIdx.x >> 5, ln = threadIdx.x & 31;
        if (ln == 0) { red[0][wp] = s; red[1][wp] = q; }
        __syncthreads();
        if (threadIdx.x == 0) {
            float S = 0.f, Q = 0.f;
            int nw = blockDim.x >> 5;
            for (int i = 0; i < nw; i++) { S += red[0][i]; Q += red[1][i]; }
            atomicAdd(&stats[c], S);
            atomicAdd(&stats[C + c], Q);
        }
    }
}

// ---------------- final: (mean of 1x1 conv of sigmoid map) * x / (mean_c x + 1e-6) ----------------
__global__ void final_kernel(const float* __restrict__ u7, const float* __restrict__ x,
                             const float* __restrict__ wm, float* __restrict__ out)
{
    int idx = blockIdx.x * 256 + threadIdx.x;   // over B*65536
    int b = idx >> 16; int p = idx & 65535;
    const float* up = u7 + (size_t)b * 32 * 65536 + p;
    float acc = wm[32];
#pragma unroll
    for (int i = 0; i < 32; i++) acc = fmaf(wm[i], up[i * 65536], acc);
    const float* xp = x + (size_t)b * 3 * 65536 + p;
    float x0 = xp[0], x1 = xp[65536], x2 = xp[131072];
    float xm = (x0 + x1 + x2) * (1.f / 3.f);
    float t = acc / (xm + 1e-6f);
    float* op = out + (size_t)b * 3 * 65536 + p;
    op[0] = t * x0; op[65536] = t * x1; op[131072] = t * x2;
}

// ---------------- orchestration ----------------
extern "C" void kernel_launch(void* const* d_in, const int* in_sizes, int n_in,
                              void* d_out, int out_size)
{
    const float* x      = (const float*)d_in[0];
    const float* n16    = (const float*)d_in[1];
    const float* sig16  = (const float*)d_in[2];
    const float* bias16 = (const float*)d_in[3];
    const float* pa     = (const float*)d_in[4];
    const float* bn3_g  = (const float*)d_in[5];
    const float* bn3_b  = (const float*)d_in[6];
    const float* bn32_g = (const float*)d_in[7];
    const float* bn32_b = (const float*)d_in[8];
    const float* bn64_g = (const float*)d_in[9];
    const float* bn64_b = (const float*)d_in[10];
    const float* bn128_g= (const float*)d_in[11];
    const float* bn128_b= (const float*)d_in[12];
    const float* w1  = (const float*)d_in[13]; const float* b1  = (const float*)d_in[14];
    const float* w2  = (const float*)d_in[15]; const float* b2  = (const float*)d_in[16];
    const float* w3  = (const float*)d_in[17]; const float* b3  = (const float*)d_in[18];
    const float* w4  = (const float*)d_in[19]; const float* b4  = (const float*)d_in[20];
    const float* w5  = (const float*)d_in[21]; const float* b5  = (const float*)d_in[22];
    const float* w6  = (const float*)d_in[23]; const float* b6  = (const float*)d_in[24];
    const float* w7  = (const float*)d_in[25]; const float* b7  = (const float*)d_in[26];
    const float* w11 = (const float*)d_in[27]; const float* b11 = (const float*)d_in[28];
    float* out = (float*)d_out;

    float *p_fusion, *p_x1, *p_x2, *p_x3, *p_x4, *p_c5, *p_x5, *p_c6, *p_x6, *p_c7, *p_u7;
    float *p_sums, *p_sc3, *p_sh3, *p_sc7, *p_sh7, *p_sc6, *p_sh6, *p_sc5, *p_sh5, *p_wm;
    cudaGetSymbolAddress((void**)&p_fusion, g_fusion);
    cudaGetSymbolAddress((void**)&p_x1, g_x1);
    cudaGetSymbolAddress((void**)&p_x2, g_x2);
    cudaGetSymbolAddress((void**)&p_x3, g_x3);
    cudaGetSymbolAddress((void**)&p_x4, g_x4);
    cudaGetSymbolAddress((void**)&p_c5, g_c5);
    cudaGetSymbolAddress((void**)&p_x5, g_x5);
    cudaGetSymbolAddress((void**)&p_c6, g_c6);
    cudaGetSymbolAddress((void**)&p_x6, g_x6);
    cudaGetSymbolAddress((void**)&p_c7, g_c7);
    cudaGetSymbolAddress((void**)&p_u7, g_u7);
    cudaGetSymbolAddress((void**)&p_sums, g_bnsums);
    cudaGetSymbolAddress((void**)&p_sc3, g_sc3); cudaGetSymbolAddress((void**)&p_sh3, g_sh3);
    cudaGetSymbolAddress((void**)&p_sc7, g_sc7); cudaGetSymbolAddress((void**)&p_sh7, g_sh7);
    cudaGetSymbolAddress((void**)&p_sc6, g_sc6); cudaGetSymbolAddress((void**)&p_sh6, g_sh6);
    cudaGetSymbolAddress((void**)&p_sc5, g_sc5); cudaGetSymbolAddress((void**)&p_sh5, g_sh5);
    cudaGetSymbolAddress((void**)&p_wm, g_wm);

    zero_stats_kernel<<<1, 992>>>(p_sums);
    finalize_w11_kernel<<<1, 33>>>(w11, b11, p_wm);

    // 16 curves + bn3 stats
    curve_kernel<<<6144, 256>>>(x, n16, sig16, bias16, p_fusion, p_sums + OFF3);
    finalize_bn_kernel<<<1, 48>>>(p_sums + OFF3, 48, 1.f / 524288.f, bn3_g, bn3_b, 3, p_sc3, p_sh3);

    // conv1 48->32 @256, prelu+pool, bn32a stats
    conv3x3_kernel<48, 0, 32, 16, 32, 16, true, true, true>
        <<<dim3(8, 16, 16), 128>>>(p_fusion, nullptr, p_sc3, p_sh3, w1, b1, pa,
                                   p_x1, p_sums + OFF32A, 256, 256);
    finalize_bn_kernel<<<1, 32>>>(p_sums + OFF32A, 32, 1.f / 131072.f, bn32_g, bn32_b, 0, p_sc7, p_sh7);

    // conv2 32->64 @128, prelu+pool, bn64a
    conv3x3_kernel<32, 0, 64, 16, 32, 16, true, true, true>
        <<<dim3(4, 8, 32), 128>>>(p_x1, nullptr, p_sc7, p_sh7, w2, b2, pa,
                                  p_x2, p_sums + OFF64A, 128, 128);
    finalize_bn_kernel<<<1, 64>>>(p_sums + OFF64A, 64, 1.f / 32768.f, bn64_g, bn64_b, 0, p_sc6, p_sh6);

    // conv3 64->128 @64, prelu+pool, bn128a
    conv3x3_kernel<64, 0, 128, 16, 32, 16, true, true, true>
        <<<dim3(2, 4, 64), 128>>>(p_x2, nullptr, p_sc6, p_sh6, w3, b3, pa,
                                  p_x3, p_sums + OFF128A, 64, 64);
    finalize_bn_kernel<<<1, 128>>>(p_sums + OFF128A, 128, 1.f / 8192.f, bn128_g, bn128_b, 0,
                                   p_sc5 + 128, p_sh5 + 128);

    // conv4 128->128 @32, no prelu/pool, bn128b
    conv3x3_kernel<128, 0, 128, 8, 16, 16, false, false, true>
        <<<dim3(2, 2, 128), 64>>>(p_x3, nullptr, p_sc5 + 128, p_sh5 + 128, w4, b4, pa,
                                  p_x4, p_sums + OFF128B, 32, 32);
    finalize_bn_kernel<<<1, 128>>>(p_sums + OFF128B, 128, 1.f / 8192.f, bn128_g, bn128_b, 0, p_sc5, p_sh5);

    // conv5 cat[x4,x3] 256->64 @32, prelu
    conv3x3_kernel<128, 128, 64, 4, 16, 16, true, false, false>
        <<<dim3(2, 2, 128), 64>>>(p_x4, p_x3, p_sc5, p_sh5, w5, b5, pa,
                                  p_c5, nullptr, 32, 32);
    // up to 64, bn64b stats
    upsample2_kernel<true, false><<<dim3(16, 64, 8), 256>>>(p_c5, p_x5, p_sums + OFF64B, 64, 32, 32);
    finalize_bn_kernel<<<1, 64>>>(p_sums + OFF64B, 64, 1.f / 32768.f, bn64_g, bn64_b, 0,
                                  p_sc6 + 64, p_sh6 + 64);

    // conv6 cat[x2,x5] 128->32 @64, prelu
    conv3x3_kernel<64, 64, 32, 8, 16, 16, true, false, false>
        <<<dim3(4, 4, 32), 64>>>(p_x2, p_x5, p_sc6, p_sh6, w6, b6, pa,
                                 p_c6, nullptr, 64, 64);
    // up to 128, bn32b stats
    upsample2_kernel<true, false><<<dim3(64, 32, 8), 256>>>(p_c6, p_x6, p_sums + OFF32B, 32, 64, 64);
    finalize_bn_kernel<<<1, 32>>>(p_sums + OFF32B, 32, 1.f / 131072.f, bn32_g, bn32_b, 0,
                                  p_sc7 + 32, p_sh7 + 32);

    // conv7 cat[x1,x6] 64->32 @128, prelu
    conv3x3_kernel<32, 32, 32, 16, 32, 16, true, false, false>
        <<<dim3(4, 8, 16), 128>>>(p_x1, p_x6, p_sc7, p_sh7, w7, b7, pa,
                                  p_c7, nullptr, 128, 128);
    // up to 256 + sigmoid
    upsample2_kernel<false, true><<<dim3(256, 32, 8), 256>>>(p_c7, p_u7, nullptr, 32, 128, 128);

    // collapsed 1x1 conv + channel-mean + ratio recombination
    final_kernel<<<2048, 256>>>(p_u7, x, p_wm, out);
}

// round 12
// speedup vs baseline: 1.0143x; 1.0143x over previous
#include <cuda_runtime.h>
#include <math.h>

// ---------------- static device scratch (no allocations allowed) ----------------
#define B_ 8
__device__ float g_fusion[B_*48*256*256];   // curve outputs, un-normalized
__device__ float g_x1[B_*32*128*128];
__device__ float g_x2[B_*64*64*64];
__device__ float g_x3[B_*128*32*32];
__device__ float g_x4[B_*128*32*32];
__device__ float g_c5[B_*64*32*32];
__device__ float g_x5[B_*64*64*64];
__device__ float g_c6[B_*32*64*64];
__device__ float g_x6[B_*32*128*128];
__device__ float g_c7[B_*32*128*128];
__device__ float g_u7[B_*32*256*256];
__device__ float g_bnsums[992];
__device__ float g_sc3[48], g_sh3[48];
__device__ float g_sc7[64], g_sh7[64];     // [bn32a | bn32b]
__device__ float g_sc6[128], g_sh6[128];   // [bn64a | bn64b]
__device__ float g_sc5[256], g_sh5[256];   // [bn128b | bn128a]
__device__ float g_wm[33];                 // channel-mean of w11, b11

// sums layout offsets (each region: [sum C][sumsq C])
#define OFF3    0    // 96
#define OFF32A  96   // 64
#define OFF64A  160  // 128
#define OFF128A 288  // 256
#define OFF128B 544  // 256
#define OFF64B  800  // 128
#define OFF32B  928  // 64

// ---------------- tiny kernels ----------------
__global__ void zero_stats_kernel(float* s) { s[threadIdx.x] = 0.f; }

__global__ void finalize_bn_kernel(const float* __restrict__ sums, int C, float invN,
                                   const float* __restrict__ gam, const float* __restrict__ bet,
                                   int gmod, float* __restrict__ sc, float* __restrict__ sh)
{
    int c = threadIdx.x;
    if (c >= C) return;
    float m = sums[c] * invN;
    float v = fmaxf(sums[C + c] * invN - m * m, 0.f);
    int gi = gmod ? (c % gmod) : c;
    float s = gam[gi] * rsqrtf(v + 1e-5f);
    sc[c] = s;
    sh[c] = bet[gi] - m * s;
}

__global__ void finalize_w11_kernel(const float* __restrict__ w11, const float* __restrict__ b11,
                                    float* __restrict__ wm)
{
    int t = threadIdx.x;
    if (t < 32)      wm[t]  = (w11[t] + w11[32 + t] + w11[64 + t]) * (1.f / 3.f);
    else if (t == 32) wm[32] = (b11[0] + b11[1] + b11[2]) * (1.f / 3.f);
}

// ---------------- curve kernel: 16 enhancement branches + BN3 stats ----------------
__global__ void curve_kernel(const float* __restrict__ x, const float* __restrict__ n16,
                             const float* __restrict__ sig, const float* __restrict__ bias,
                             float* __restrict__ fusion, float* __restrict__ sums)
{
    __shared__ float s_n[16], s_d[16];
    int tid = threadIdx.x;
    if (tid < 16) {
        float n = n16[tid];
        s_n[tid] = n;
        s_d[tid] = exp2f(n * log2f(sig[tid])) + bias[tid];
    }
    __syncthreads();

    int idx = blockIdx.x * 256 + tid;         // over B*3*256*256, one row per block
    int hw = idx & 65535;
    int bc = idx >> 16;
    int c = bc % 3, b = bc / 3;

    float xv = x[idx];
    float l = log2f(xv);
    float sm[16], sq[16];
#pragma unroll
    for (int k = 0; k < 16; k++) {
        float xn = exp2f(s_n[k] * l);
        float r = xn / (xn + s_d[k]);
        fusion[((b * 48 + k * 3 + c) << 16) + hw] = r;
        sm[k] = r; sq[k] = r * r;
    }
    // warp reduce each of 16 (sum,sq)
#pragma unroll
    for (int k = 0; k < 16; k++) {
        float s = sm[k], q = sq[k];
        for (int o = 16; o; o >>= 1) {
            s += __shfl_xor_sync(0xFFFFFFFFu, s, o);
            q += __shfl_xor_sync(0xFFFFFFFFu, q, o);
        }
        sm[k] = s; sq[k] = q;
    }
    __shared__ float red[16][2][8];
    int wp = tid >> 5, ln = tid & 31;
    if (ln == 0) {
#pragma unroll
        for (int k = 0; k < 16; k++) { red[k][0][wp] = sm[k]; red[k][1][wp] = sq[k]; }
    }
    __syncthreads();
    if (tid < 32) {
        int k = tid >> 1, which = tid & 1;
        float v = 0.f;
#pragma unroll
        for (int i = 0; i < 8; i++) v += red[k][which][i];
        atomicAdd(&sums[which * 48 + k * 3 + c], v);
    }
}

// ---------------- templated 3x3 conv (+affine-in, +bias, +prelu, +pool, +stats) ----------------
template<int CIN0, int CIN1, int COUT, int COG, int TW, int TH, bool PRELU, bool POOL, bool STATS>
__global__ void __launch_bounds__((TW / 2) * (TH / 2))
conv3x3_kernel(const float* __restrict__ in0, const float* __restrict__ in1,
               const float* __restrict__ sc, const float* __restrict__ sh,
               const float* __restrict__ Wt, const float* __restrict__ Bs,
               const float* __restrict__ pa_ptr,
               float* __restrict__ out, float* __restrict__ stats,
               int H, int Wd)
{
    constexpr int CIN = CIN0 + CIN1;
    constexpr int CH = 8;
    constexpr int NT = (TW / 2) * (TH / 2);
    constexpr int IW = TW + 3;     // padded row stride (odd) to cut bank conflicts
    constexpr int NW = NT / 32;

    __shared__ float s_in[CH][TH + 2][IW];
    __shared__ float s_w[CH * 9 * COG];
    __shared__ float red[2][COG][NW];

    int tid = threadIdx.x;
    constexpr int GPB = COUT / COG;
    int b = blockIdx.z / GPB, g = blockIdx.z % GPB;
    int tx = blockIdx.x * TW, ty = blockIdx.y * TH;
    float pa = PRELU ? pa_ptr[0] : 0.f;

    float acc[4 * COG];
#pragma unroll
    for (int i = 0; i < 4 * COG; i++) acc[i] = 0.f;

    int qx = (tid % (TW / 2)) * 2, qy = (tid / (TW / 2)) * 2;

    for (int c0 = 0; c0 < CIN; c0 += CH) {
        // cooperative input tile load (affine applied; OOB -> 0 = post-BN zero pad)
        constexpr int TOT = CH * (TH + 2) * (TW + 2);
        for (int i = tid; i < TOT; i += NT) {
            int ci = i / ((TH + 2) * (TW + 2));
            int r = i - ci * ((TH + 2) * (TW + 2));
            int ly = r / (TW + 2), lx = r - ly * (TW + 2);
            int gy = ty + ly - 1, gx = tx + lx - 1;
            int cg = c0 + ci;
            float v = 0.f;
            if (gy >= 0 && gy < H && gx >= 0 && gx < Wd) {
                float raw;
                if (CIN1 == 0 || cg < CIN0)
                    raw = in0[((b * CIN0 + cg) * H + gy) * Wd + gx];
                else
                    raw = in1[((b * CIN1 + (cg - CIN0)) * H + gy) * Wd + gx];
                v = fmaf(raw, sc[cg], sh[cg]);
            }
            s_in[ci][ly][lx] = v;
        }
        // weight chunk load: layout [ci][tap][co]
        for (int i = tid; i < CH * 9 * COG; i += NT) {
            int co = i % COG; int t2 = i / COG; int tap = t2 % 9; int ci = t2 / 9;
            s_w[i] = Wt[((g * COG + co) * CIN + c0 + ci) * 9 + tap];
        }
        __syncthreads();

        for (int ci = 0; ci < CH; ci++) {
            float iv[4][4];
#pragma unroll
            for (int a = 0; a < 4; a++)
#pragma unroll
                for (int bb = 0; bb < 4; bb++) iv[a][bb] = s_in[ci][qy + a][qx + bb];
#pragma unroll
            for (int dy = 0; dy < 3; dy++)
#pragma unroll
                for (int dx = 0; dx < 3; dx++) {
                    const float* wrow = &s_w[(ci * 9 + dy * 3 + dx) * COG];
#pragma unroll
                    for (int co = 0; co < COG; co++) {
                        float wv = wrow[co];  // broadcast LDS feeds 4 FFMAs
                        acc[co * 4 + 0] += wv * iv[dy][dx];
                        acc[co * 4 + 1] += wv * iv[dy][dx + 1];
                        acc[co * 4 + 2] += wv * iv[dy + 1][dx];
                        acc[co * 4 + 3] += wv * iv[dy + 1][dx + 1];
                    }
                }
        }
        __syncthreads();
    }

    // epilogue: bias, prelu, pool, store, BN-stat accumulate
    int wp = tid >> 5, ln = tid & 31;
    int HO = POOL ? H / 2 : H, WO = POOL ? Wd / 2 : Wd;
#pragma unroll
    for (int co = 0; co < COG; co++) {
        int gco = g * COG + co;
        float bsv = Bs[gco];
        float v0 = acc[co * 4 + 0] + bsv, v1 = acc[co * 4 + 1] + bsv;
        float v2 = acc[co * 4 + 2] + bsv, v3 = acc[co * 4 + 3] + bsv;
        if (PRELU) {
            v0 = v0 >= 0.f ? v0 : pa * v0; v1 = v1 >= 0.f ? v1 : pa * v1;
            v2 = v2 >= 0.f ? v2 : pa * v2; v3 = v3 >= 0.f ? v3 : pa * v3;
        }
        float ssum, ssq;
        if (POOL) {
            float m = fmaxf(fmaxf(v0, v1), fmaxf(v2, v3));
            int oy = (ty + qy) >> 1, ox = (tx + qx) >> 1;
            out[((b * COUT + gco) * HO + oy) * WO + ox] = m;
            ssum = m; ssq = m * m;
        } else {
            int oy = ty + qy, ox = tx + qx;
            float* op = &out[((b * COUT + gco) * HO + oy) * WO + ox];
            op[0] = v0; op[1] = v1; op[WO] = v2; op[WO + 1] = v3;
            ssum = v0 + v1 + v2 + v3;
            ssq = v0 * v0 + v1 * v1 + v2 * v2 + v3 * v3;
        }
        if (STATS) {
            for (int o = 16; o; o >>= 1) {
                ssum += __shfl_xor_sync(0xFFFFFFFFu, ssum, o);
                ssq  += __shfl_xor_sync(0xFFFFFFFFu, ssq, o);
            }
            if (ln == 0) { red[0][co][wp] = ssum; red[1][co][wp] = ssq; }
        }
    }
    if (STATS) {
        __syncthreads();
        if (tid < 2 * COG) {
            int which = tid / COG, co = tid % COG;
            float v = 0.f;
#pragma unroll
            for (int i = 0; i < NW; i++) v += red[which][co][i];
            atomicAdd(&stats[which * COUT + g * COG + co], v);
        }
    }
}

// ---------------- bilinear x2 upsample (align_corners), optional stats / sigmoid ----------------
template<bool STATS, bool SIG>
__global__ void upsample2_kernel(const float* __restrict__ in, float* __restrict__ out,
                                 float* __restrict__ stats, int C, int H, int Wd)
{
    int H2 = 2 * H, W2 = 2 * Wd;
    int c = blockIdx.y, b = blockIdx.z;
    int idx = blockIdx.x * blockDim.x + threadIdx.x;
    int oy = idx / W2, ox = idx % W2;

    float py = (float)(oy * (H - 1)) / (float)(2 * H - 1);
    int ly = (int)floorf(py); int hy = min(ly + 1, H - 1); float fy = py - (float)ly;
    float px = (float)(ox * (Wd - 1)) / (float)(2 * Wd - 1);
    int lx = (int)floorf(px); int hx = min(lx + 1, Wd - 1); float fx = px - (float)lx;

    const float* ip = in + ((size_t)(b * C + c) * H) * Wd;
    float a00 = ip[ly * Wd + lx], a01 = ip[ly * Wd + hx];
    float a10 = ip[hy * Wd + lx], a11 = ip[hy * Wd + hx];
    float r0 = a00 * (1.f - fy) + a10 * fy;     // rows first (matches reference order)
    float r1 = a01 * (1.f - fy) + a11 * fy;
    float v = r0 * (1.f - fx) + r1 * fx;
    if (SIG) v = 1.f / (1.f + expf(-v));
    out[((size_t)(b * C + c) * H2 + oy) * W2 + ox] = v;

    if (STATS) {
        float s = v, q = v * v;
        for (int o = 16; o; o >>= 1) {
            s += __shfl_xor_sync(0xFFFFFFFFu, s, o);
            q += __shfl_xor_sync(0xFFFFFFFFu, q, o);
        }
        __shared__ float red[2][8];
        int wp = threadIdx.x >> 5, ln = threadIdx.x & 31;
        if (ln == 0) { red[0][wp] = s; red[1][wp] = q; }
        __syncthreads();
        if (threadIdx.x == 0) {
            float S = 0.f, Q = 0.f;
            int nw = blockDim.x >> 5;
            for (int i = 0; i < nw; i++) { S += red[0][i]; Q += red[1][i]; }
            atomicAdd(&stats[c], S);
            atomicAdd(&stats[C + c], Q);
        }
    }
}

// ---------------- final: (mean of 1x1 conv of sigmoid map) * x / (mean_c x + 1e-6) ----------------
__global__ void final_kernel(const float* __restrict__ u7, const float* __restrict__ x,
                             const float* __restrict__ wm, float* __restrict__ out)
{
    int idx = blockIdx.x * 256 + threadIdx.x;   // over B*65536
    int b = idx >> 16; int p = idx & 65535;
    const float* up = u7 + (size_t)b * 32 * 65536 + p;
    float acc = wm[32];
#pragma unroll
    for (int i = 0; i < 32; i++) acc = fmaf(wm[i], up[i * 65536], acc);
    const float* xp = x + (size_t)b * 3 * 65536 + p;
    float x0 = xp[0], x1 = xp[65536], x2 = xp[131072];
    float xm = (x0 + x1 + x2) * (1.f / 3.f);
    float t = acc / (xm + 1e-6f);
    float* op = out + (size_t)b * 3 * 65536 + p;
    op[0] = t * x0; op[65536] = t * x1; op[131072] = t * x2;
}

// ---------------- orchestration ----------------
extern "C" void kernel_launch(void* const* d_in, const int* in_sizes, int n_in,
                              void* d_out, int out_size)
{
    const float* x      = (const float*)d_in[0];
    const float* n16    = (const float*)d_in[1];
    const float* sig16  = (const float*)d_in[2];
    const float* bias16 = (const float*)d_in[3];
    const float* pa     = (const float*)d_in[4];
    const float* bn3_g  = (const float*)d_in[5];
    const float* bn3_b  = (const float*)d_in[6];
    const float* bn32_g = (const float*)d_in[7];
    const float* bn32_b = (const float*)d_in[8];
    const float* bn64_g = (const float*)d_in[9];
    const float* bn64_b = (const float*)d_in[10];
    const float* bn128_g= (const float*)d_in[11];
    const float* bn128_b= (const float*)d_in[12];
    const float* w1  = (const float*)d_in[13]; const float* b1  = (const float*)d_in[14];
    const float* w2  = (const float*)d_in[15]; const float* b2  = (const float*)d_in[16];
    const float* w3  = (const float*)d_in[17]; const float* b3  = (const float*)d_in[18];
    const float* w4  = (const float*)d_in[19]; const float* b4  = (const float*)d_in[20];
    const float* w5  = (const float*)d_in[21]; const float* b5  = (const float*)d_in[22];
    const float* w6  = (const float*)d_in[23]; const float* b6  = (const float*)d_in[24];
    const float* w7  = (const float*)d_in[25]; const float* b7  = (const float*)d_in[26];
    const float* w11 = (const float*)d_in[27]; const float* b11 = (const float*)d_in[28];
    float* out = (float*)d_out;

    float *p_fusion, *p_x1, *p_x2, *p_x3, *p_x4, *p_c5, *p_x5, *p_c6, *p_x6, *p_c7, *p_u7;
    float *p_sums, *p_sc3, *p_sh3, *p_sc7, *p_sh7, *p_sc6, *p_sh6, *p_sc5, *p_sh5, *p_wm;
    cudaGetSymbolAddress((void**)&p_fusion, g_fusion);
    cudaGetSymbolAddress((void**)&p_x1, g_x1);
    cudaGetSymbolAddress((void**)&p_x2, g_x2);
    cudaGetSymbolAddress((void**)&p_x3, g_x3);
    cudaGetSymbolAddress((void**)&p_x4, g_x4);
    cudaGetSymbolAddress((void**)&p_c5, g_c5);
    cudaGetSymbolAddress((void**)&p_x5, g_x5);
    cudaGetSymbolAddress((void**)&p_c6, g_c6);
    cudaGetSymbolAddress((void**)&p_x6, g_x6);
    cudaGetSymbolAddress((void**)&p_c7, g_c7);
    cudaGetSymbolAddress((void**)&p_u7, g_u7);
    cudaGetSymbolAddress((void**)&p_sums, g_bnsums);
    cudaGetSymbolAddress((void**)&p_sc3, g_sc3); cudaGetSymbolAddress((void**)&p_sh3, g_sh3);
    cudaGetSymbolAddress((void**)&p_sc7, g_sc7); cudaGetSymbolAddress((void**)&p_sh7, g_sh7);
    cudaGetSymbolAddress((void**)&p_sc6, g_sc6); cudaGetSymbolAddress((void**)&p_sh6, g_sh6);
    cudaGetSymbolAddress((void**)&p_sc5, g_sc5); cudaGetSymbolAddress((void**)&p_sh5, g_sh5);
    cudaGetSymbolAddress((void**)&p_wm, g_wm);

    zero_stats_kernel<<<1, 992>>>(p_sums);
    finalize_w11_kernel<<<1, 33>>>(w11, b11, p_wm);

    // 16 curves + bn3 stats
    curve_kernel<<<6144, 256>>>(x, n16, sig16, bias16, p_fusion, p_sums + OFF3);
    finalize_bn_kernel<<<1, 48>>>(p_sums + OFF3, 48, 1.f / 524288.f, bn3_g, bn3_b, 3, p_sc3, p_sh3);

    // conv1 48->32 @256, prelu+pool, bn32a stats
    conv3x3_kernel<48, 0, 32, 16, 32, 16, true, true, true>
        <<<dim3(8, 16, 16), 128>>>(p_fusion, nullptr, p_sc3, p_sh3, w1, b1, pa,
                                   p_x1, p_sums + OFF32A, 256, 256);
    finalize_bn_kernel<<<1, 32>>>(p_sums + OFF32A, 32, 1.f / 131072.f, bn32_g, bn32_b, 0, p_sc7, p_sh7);

    // conv2 32->64 @128, prelu+pool, bn64a
    conv3x3_kernel<32, 0, 64, 16, 32, 16, true, true, true>
        <<<dim3(4, 8, 32), 128>>>(p_x1, nullptr, p_sc7, p_sh7, w2, b2, pa,
                                  p_x2, p_sums + OFF64A, 128, 128);
    finalize_bn_kernel<<<1, 64>>>(p_sums + OFF64A, 64, 1.f / 32768.f, bn64_g, bn64_b, 0, p_sc6, p_sh6);

    // conv3 64->128 @64, prelu+pool, bn128a
    conv3x3_kernel<64, 0, 128, 16, 32, 16, true, true, true>
        <<<dim3(2, 4, 64), 128>>>(p_x2, nullptr, p_sc6, p_sh6, w3, b3, pa,
                                  p_x3, p_sums + OFF128A, 64, 64);
    finalize_bn_kernel<<<1, 128>>>(p_sums + OFF128A, 128, 1.f / 8192.f, bn128_g, bn128_b, 0,
                                   p_sc5 + 128, p_sh5 + 128);

    // conv4 128->128 @32, no prelu/pool, bn128b
    conv3x3_kernel<128, 0, 128, 8, 16, 16, false, false, true>
        <<<dim3(2, 2, 128), 64>>>(p_x3, nullptr, p_sc5 + 128, p_sh5 + 128, w4, b4, pa,
                                  p_x4, p_sums + OFF128B, 32, 32);
    finalize_bn_kernel<<<1, 128>>>(p_sums + OFF128B, 128, 1.f / 8192.f, bn128_g, bn128_b, 0, p_sc5, p_sh5);

    // conv5 cat[x4,x3] 256->64 @32, prelu
    conv3x3_kernel<128, 128, 64, 4, 16, 16, true, false, false>
        <<<dim3(2, 2, 128), 64>>>(p_x4, p_x3, p_sc5, p_sh5, w5, b5, pa,
                                  p_c5, nullptr, 32, 32);
    // up to 64, bn64b stats
    upsample2_kernel<true, false><<<dim3(16, 64, 8), 256>>>(p_c5, p_x5, p_sums + OFF64B, 64, 32, 32);
    finalize_bn_kernel<<<1, 64>>>(p_sums + OFF64B, 64, 1.f / 32768.f, bn64_g, bn64_b, 0,
                                  p_sc6 + 64, p_sh6 + 64);

    // conv6 cat[x2,x5] 128->32 @64, prelu
    conv3x3_kernel<64, 64, 32, 8, 16, 16, true, false, false>
        <<<dim3(4, 4, 32), 64>>>(p_x2, p_x5, p_sc6, p_sh6, w6, b6, pa,
                                 p_c6, nullptr, 64, 64);
    // up to 128, bn32b stats
    upsample2_kernel<true, false><<<dim3(64, 32, 8), 256>>>(p_c6, p_x6, p_sums + OFF32B, 32, 64, 64);
    finalize_bn_kernel<<<1, 32>>>(p_sums + OFF32B, 32, 1.f / 131072.f, bn32_g, bn32_b, 0,
                                  p_sc7 + 32, p_sh7 + 32);

    // conv7 cat[x1,x6] 64->32 @128, prelu
    conv3x3_kernel<32, 32, 32, 16, 32, 16, true, false, false>
        <<<dim3(4, 8, 16), 128>>>(p_x1, p_x6, p_sc7, p_sh7, w7, b7, pa,
                                  p_c7, nullptr, 128, 128);
    // up to 256 + sigmoid
    upsample2_kernel<false, true><<<dim3(256, 32, 8), 256>>>(p_c7, p_u7, nullptr, 32, 128, 128);

    // collapsed 1x1 conv + channel-mean + ratio recombination
    final_kernel<<<2048, 256>>>(p_u7, x, p_wm, out);
}